// round 12
// baseline (speedup 1.0000x reference)
#include <cuda_runtime.h>
#include <math.h>

#define NN    512
#define BIT   64
#define NCLS  100
#define ALPHA 5.0f
#define LAM   1.0f
#define RPB   2                 // anchor rows per block
#define NB    (NN / RPB)        // 256 blocks
#define NT    256               // threads per block

// Scratch (allocation-free: __device__ globals)
__device__ float4 g_part[NB];    // {bsum, bcnt, bl2, 0} per block
__device__ unsigned int g_done = 0;

// ---------------------------------------------------------------------------
// Single fused kernel, two anchor rows per block (halves total u LDG traffic
// vs R11 while keeping coalesced loads). Last block reduces + writes output.
// ---------------------------------------------------------------------------
__global__ void __launch_bounds__(NT) fused_kernel(const float* __restrict__ u,
                                                   const float* __restrict__ y,
                                                   float* __restrict__ out) {
    __shared__ float4 s_ur[RPB][BIT / 4];          // anchor rows of u     (512 B)
    __shared__ float  s_ip[RPB][NN];               // ip rows              (4 KB)
    __shared__ int    s_lbl[RPB];
    __shared__ unsigned s_gmask[RPB][16];          // pos bitmask words
    __shared__ short  s_poslist[RPB][NN];          // positive indices     (2 KB)
    __shared__ float  s_part[RPB][8];              // per-warp pair partials
    __shared__ float  s_s2[4];                     // loss2 partials
    __shared__ int    s_islast;
    __shared__ float4 s_rf[NT];                    // final reduce scratch (4 KB)

    const int tid  = threadIdx.x;
    const int bid  = blockIdx.x;
    const int r0   = bid * RPB;
    const int lane = tid & 31;
    const int wrp  = tid >> 5;

    // --- phase 0: anchor rows of u into smem + label recovery (one-hot) ---
    if (tid < RPB * (BIT / 4)) {                   // 32 float4 loads
        int i = tid >> 4;
        int k = tid & 15;
        s_ur[i][k] = ((const float4*)(u + (size_t)(r0 + i) * BIT))[k];
    }
    if (tid < RPB * NCLS) {                        // 200 <= 256, one writer/row
        int i = tid / NCLS;
        int c = tid % NCLS;
        if (y[(size_t)(r0 + i) * NCLS + c] > 0.5f) s_lbl[i] = c;
    }
    __syncthreads();

    const int lbl0 = s_lbl[0];
    const int lbl1 = s_lbl[1];

    // --- scattered isneg gathers issued EARLY; hide under the dot loop ---
    const float yv00 = __ldg(y + (size_t)tid * NCLS + lbl0);          // row0, j=tid
    const float yv01 = __ldg(y + (size_t)(tid + NT) * NCLS + lbl0);   // row0, j=tid+256
    const float yv10 = __ldg(y + (size_t)tid * NCLS + lbl1);          // row1, j=tid
    const float yv11 = __ldg(y + (size_t)(tid + NT) * NCLS + lbl1);   // row1, j=tid+256

    // --- coalesced dot phase: 16-lane segments, 16 rows / iter, 2 anchors ---
    {
        const float4 av0 = s_ur[0][tid & 15];
        const float4 av1 = s_ur[1][tid & 15];
        const int seg = tid & 15;
        const int row_in_iter = tid >> 4;
        #pragma unroll 8
        for (int it = 0; it < NN / 16; ++it) {
            float4 b = ((const float4*)u)[it * (16 * BIT / 4) + tid];
            float p0 = av0.x * b.x + av0.y * b.y + av0.z * b.z + av0.w * b.w;
            float p1 = av1.x * b.x + av1.y * b.y + av1.z * b.z + av1.w * b.w;
            #pragma unroll
            for (int o = 1; o < 16; o <<= 1) {
                p0 += __shfl_xor_sync(0xffffffffu, p0, o);
                p1 += __shfl_xor_sync(0xffffffffu, p1, o);
            }
            if (seg == 0) {
                s_ip[0][it * 16 + row_in_iter] = p0;
                s_ip[1][it * 16 + row_in_iter] = p1;
            }
        }
    }

    // --- isneg in registers (one-hot: exact 0/1); ballots from registers ---
    const bool n00 = (yv00 == 0.0f);
    const bool n01 = (yv01 == 0.0f);
    const bool n10 = (yv10 == 0.0f);
    const bool n11 = (yv11 == 0.0f);
    {
        unsigned m;
        m = __ballot_sync(0xffffffffu, !n00);
        if (lane == 0) s_gmask[0][wrp] = m;
        m = __ballot_sync(0xffffffffu, !n01);
        if (lane == 0) s_gmask[0][wrp + 8] = m;
        m = __ballot_sync(0xffffffffu, !n10);
        if (lane == 0) s_gmask[1][wrp] = m;
        m = __ballot_sync(0xffffffffu, !n11);
        if (lane == 0) s_gmask[1][wrp + 8] = m;
    }

    // --- loss2 partial: this block's RPB*BIT = 128 u values (smem copy) ---
    if (tid < RPB * BIT) {
        float v  = ((const float*)s_ur)[tid];
        float sg = (v > 0.0f) ? 1.0f : ((v < 0.0f) ? -1.0f : 0.0f);
        float d  = v - sg;
        float s2 = d * d;
        #pragma unroll
        for (int o = 16; o > 0; o >>= 1) s2 += __shfl_xor_sync(0xffffffffu, s2, o);
        if (lane == 0) s_s2[wrp] = s2;
    }
    __syncthreads();

    // --- fully parallel rank-based compaction (both rows) ---
    int npos0 = 0, npos1 = 0;
    {
        int ra0 = 0, rb0 = 0, ra1 = 0, rb1 = 0;
        #pragma unroll
        for (int c = 0; c < 16; ++c) {
            int p0 = __popc(s_gmask[0][c]);
            int p1 = __popc(s_gmask[1][c]);
            if (c < wrp)     { ra0 += p0; ra1 += p1; }
            if (c < wrp + 8) { rb0 += p0; rb1 += p1; }
            npos0 += p0;
            npos1 += p1;
        }
        unsigned lanebits = (lane == 0) ? 0u : ((1u << lane) - 1u);
        ra0 += __popc(s_gmask[0][wrp]     & lanebits);
        rb0 += __popc(s_gmask[0][wrp + 8] & lanebits);
        ra1 += __popc(s_gmask[1][wrp]     & lanebits);
        rb1 += __popc(s_gmask[1][wrp + 8] & lanebits);
        if (!n00) s_poslist[0][ra0] = (short)tid;
        if (!n01) s_poslist[0][rb0] = (short)(tid + NT);
        if (!n10) s_poslist[1][ra1] = (short)tid;
        if (!n11) s_poslist[1][rb1] = (short)(tid + NT);
    }
    __syncthreads();

    // --- inverted pair loops: thread owns n = tid, tid+256 for both rows ---
    {
        float acc0 = 0.0f;
        const float i00 = s_ip[0][tid];
        const float i01 = s_ip[0][tid + NT];
        for (int k = 0; k < npos0; ++k) {
            float ipp = s_ip[0][s_poslist[0][k]];        // broadcast LDS
            if (n00) {
                float t = ipp - i00 - ALPHA;
                t = fminf(fmaxf(t, -100.0f), 50.0f);
                acc0 += __logf(1.0f + __expf(-fabsf(t))) + fmaxf(-t, 0.0f);
            }
            if (n01) {
                float t = ipp - i01 - ALPHA;
                t = fminf(fmaxf(t, -100.0f), 50.0f);
                acc0 += __logf(1.0f + __expf(-fabsf(t))) + fmaxf(-t, 0.0f);
            }
        }
        #pragma unroll
        for (int o = 16; o > 0; o >>= 1) acc0 += __shfl_xor_sync(0xffffffffu, acc0, o);
        if (lane == 0) s_part[0][wrp] = acc0;

        float acc1 = 0.0f;
        const float i10 = s_ip[1][tid];
        const float i11 = s_ip[1][tid + NT];
        for (int k = 0; k < npos1; ++k) {
            float ipp = s_ip[1][s_poslist[1][k]];
            if (n10) {
                float t = ipp - i10 - ALPHA;
                t = fminf(fmaxf(t, -100.0f), 50.0f);
                acc1 += __logf(1.0f + __expf(-fabsf(t))) + fmaxf(-t, 0.0f);
            }
            if (n11) {
                float t = ipp - i11 - ALPHA;
                t = fminf(fmaxf(t, -100.0f), 50.0f);
                acc1 += __logf(1.0f + __expf(-fabsf(t))) + fmaxf(-t, 0.0f);
            }
        }
        #pragma unroll
        for (int o = 16; o > 0; o >>= 1) acc1 += __shfl_xor_sync(0xffffffffu, acc1, o);
        if (lane == 0) s_part[1][wrp] = acc1;
    }
    __syncthreads();

    // --- block epilogue: 2 row losses + loss2 partial, publish ---
    if (tid == 0) {
        float bsum = 0.0f, bcnt = 0.0f;
        const int nposv[RPB] = {npos0, npos1};
        #pragma unroll
        for (int g = 0; g < RPB; ++g) {
            int   np = nposv[g];
            int   nn = NN - np;
            float rs = 0.0f;
            #pragma unroll
            for (int w2 = 0; w2 < 8; ++w2) rs += s_part[g][w2];
            float rl = rs / fmaxf((float)(np * nn), 1.0f);
            if (np > 0 && nn > 0) { bsum += rl; bcnt += 1.0f; }
        }
        float bl2 = s_s2[0] + s_s2[1] + s_s2[2] + s_s2[3];

        g_part[bid] = make_float4(bsum, bcnt, bl2, 0.0f);
        __threadfence();
        unsigned prev = atomicAdd(&g_done, 1u);
        s_islast = (prev == NB - 1) ? 1 : 0;
    }
    __syncthreads();

    // --- last block performs the final deterministic reduction ---
    if (s_islast) {
        s_rf[tid] = __ldcg(&g_part[tid]);              // NB == NT
        __syncthreads();
        #pragma unroll
        for (int s = NT / 2; s > 0; s >>= 1) {
            if (tid < s) {
                float4 x0 = s_rf[tid];
                float4 x1 = s_rf[tid + s];
                s_rf[tid] = make_float4(x0.x + x1.x, x0.y + x1.y, x0.z + x1.z, 0.0f);
            }
            __syncthreads();
        }
        if (tid == 0) {
            float4 rres = s_rf[0];
            float count = rres.y;
            float loss1 = (count > 0.0f) ? (rres.x / fmaxf(count, 1.0f)) : 0.0f;
            float loss2 = LAM * rres.z / (float)(NN * BIT);
            out[0] = loss1 + loss2;
            g_done = 0;   // reset for next graph replay (safe: we are last)
        }
    }
}

// ---------------------------------------------------------------------------
extern "C" void kernel_launch(void* const* d_in, const int* in_sizes, int n_in,
                              void* d_out, int out_size) {
    const float* u;
    const float* y;
    if (in_sizes[0] == NN * BIT) {
        u = (const float*)d_in[0];
        y = (const float*)d_in[1];
    } else {
        u = (const float*)d_in[1];
        y = (const float*)d_in[0];
    }
    float* out = (float*)d_out;

    fused_kernel<<<NB, NT>>>(u, y, out);
}

// round 13
// speedup vs baseline: 1.1530x; 1.1530x over previous
#include <cuda_runtime.h>
#include <math.h>

#define NN    512
#define BIT   64
#define NCLS  100
#define ALPHA 5.0f
#define LAM   1.0f
#define NB    NN                // 512 blocks, one anchor row each
#define NT    256               // threads per block

// Scratch (allocation-free: __device__ globals)
__device__ float4 g_part[NB];    // {rowloss_or_0, valid, l2partial, 0} per block
__device__ unsigned int g_done = 0;

// ---------------------------------------------------------------------------
// Single fused kernel, one anchor row per block. R13: dot phase uses only a
// 2-level shuffle (4-lane partial sums) + deferred per-row reduction from
// smem quarter-partials; n-side ip values stay in registers for the pair loop.
// ---------------------------------------------------------------------------
__global__ void __launch_bounds__(NT) fused_kernel(const float* __restrict__ u,
                                                   const float* __restrict__ y,
                                                   float* __restrict__ out) {
    __shared__ float4 s_ur[BIT / 4];               // anchor row of u      (256 B)
    __shared__ float4 s_pp[NN];                    // quarter partials     (8 KB)
    __shared__ float  s_ip[NN];                    // ip row               (2 KB)
    __shared__ int    s_lbl;
    __shared__ unsigned s_gmask[16];               // pos bitmask words
    __shared__ short  s_poslist[NN];               // positive indices     (1 KB)
    __shared__ float  s_part[8];                   // per-warp pair partials
    __shared__ float  s_s2[2];                     // loss2 partials (2 warps)
    __shared__ int    s_islast;
    __shared__ float4 s_rf[NT];                    // final reduce scratch (4 KB)

    const int tid  = threadIdx.x;
    const int bid  = blockIdx.x;
    const int r    = bid;                          // anchor row
    const int lane = tid & 31;
    const int wrp  = tid >> 5;

    // --- phase 0: anchor row of u into smem + label recovery (one-hot) ---
    if (tid < BIT / 4) {                           // 16 float4 loads
        s_ur[tid] = ((const float4*)(u + (size_t)r * BIT))[tid];
    }
    if (tid < NCLS) {                              // exactly one writer
        if (y[(size_t)r * NCLS + tid] > 0.5f) s_lbl = tid;
    }
    __syncthreads();                               // barrier 1

    const int lbl = s_lbl;

    // --- scattered isneg gathers issued EARLY; hide under the dot loop ---
    const float yv1 = __ldg(y + (size_t)tid * NCLS + lbl);
    const float yv2 = __ldg(y + (size_t)(tid + NT) * NCLS + lbl);

    // --- coalesced dot phase: 2-level shuffle -> quarter partials in smem ---
    {
        const float4 av = s_ur[tid & 15];
        const int row_in_iter = tid >> 4;          // 0..15
        const int q = (lane >> 2) & 3;             // quarter within row
        const bool writer = ((lane & 3) == 0);
        #pragma unroll 8
        for (int it = 0; it < NN / 16; ++it) {
            float4 b = ((const float4*)u)[it * (16 * BIT / 4) + tid];
            float p = av.x * b.x + av.y * b.y + av.z * b.z + av.w * b.w;
            p += __shfl_xor_sync(0xffffffffu, p, 1);
            p += __shfl_xor_sync(0xffffffffu, p, 2);
            if (writer) ((float*)&s_pp[it * 16 + row_in_iter])[q] = p;
        }
    }

    // --- isneg in registers (one-hot: exact 0/1); ballots from registers ---
    const bool n1 = (yv1 == 0.0f);                 // true = negative pair
    const bool n2 = (yv2 == 0.0f);
    {
        unsigned m;
        m = __ballot_sync(0xffffffffu, !n1);       // positives, j = wrp*32+lane
        if (lane == 0) s_gmask[wrp] = m;
        m = __ballot_sync(0xffffffffu, !n2);       // positives, j = 256 + ...
        if (lane == 0) s_gmask[wrp + 8] = m;
    }

    // --- loss2 partial: this block's BIT = 64 u values (from smem copy) ---
    if (tid < BIT) {
        float v  = ((const float*)s_ur)[tid];
        float sg = (v > 0.0f) ? 1.0f : ((v < 0.0f) ? -1.0f : 0.0f);
        float d  = v - sg;
        float s2 = d * d;
        #pragma unroll
        for (int o = 16; o > 0; o >>= 1) s2 += __shfl_xor_sync(0xffffffffu, s2, o);
        if (lane == 0) s_s2[wrp] = s2;
    }
    __syncthreads();                               // barrier 2

    // --- deferred row reduction: ip for own two n's straight to registers ---
    float4 q1 = s_pp[tid];
    float4 q2 = s_pp[tid + NT];
    const float ip1 = (q1.x + q1.y) + (q1.z + q1.w);
    const float ip2 = (q2.x + q2.y) + (q2.z + q2.w);
    s_ip[tid]      = ip1;
    s_ip[tid + NT] = ip2;

    // --- fully parallel rank-based compaction of positive indices ---
    int npos = 0;
    {
        int rank1 = 0, rank2 = 0;
        #pragma unroll
        for (int c = 0; c < 16; ++c) {
            int pc = __popc(s_gmask[c]);
            if (c < wrp)     rank1 += pc;
            if (c < wrp + 8) rank2 += pc;
            npos += pc;
        }
        unsigned lanebits = (lane == 0) ? 0u : ((1u << lane) - 1u);
        rank1 += __popc(s_gmask[wrp]     & lanebits);
        rank2 += __popc(s_gmask[wrp + 8] & lanebits);
        if (!n1) s_poslist[rank1] = (short)tid;
        if (!n2) s_poslist[rank2] = (short)(tid + NT);
    }
    __syncthreads();                               // barrier 3

    // --- inverted pair loop: thread owns n = tid and tid+256 (regs);
    //     loop over ~npos positives with broadcast s_ip reads ---
    float acc = 0.0f;
    for (int k = 0; k < npos; ++k) {
        float ipp = s_ip[s_poslist[k]] - ALPHA;    // broadcast LDS
        if (n1) {
            float t = ipp - ip1;
            t = fminf(fmaxf(t, -100.0f), 50.0f);
            acc += __logf(1.0f + __expf(-fabsf(t))) + fmaxf(-t, 0.0f);
        }
        if (n2) {
            float t = ipp - ip2;
            t = fminf(fmaxf(t, -100.0f), 50.0f);
            acc += __logf(1.0f + __expf(-fabsf(t))) + fmaxf(-t, 0.0f);
        }
    }
    #pragma unroll
    for (int o = 16; o > 0; o >>= 1) acc += __shfl_xor_sync(0xffffffffu, acc, o);
    if (lane == 0) s_part[wrp] = acc;
    __syncthreads();                               // barrier 4

    // --- block epilogue: row loss + loss2 partial, publish, count arrival ---
    if (tid == 0) {
        int   np = npos;
        int   nn = NN - np;
        float rs = 0.0f;
        #pragma unroll
        for (int w2 = 0; w2 < 8; ++w2) rs += s_part[w2];
        float rl    = rs / fmaxf((float)(np * nn), 1.0f);
        float valid = (np > 0 && nn > 0) ? 1.0f : 0.0f;
        float bl2   = s_s2[0] + s_s2[1];

        g_part[bid] = make_float4(valid * rl, valid, bl2, 0.0f);
        __threadfence();
        unsigned prev = atomicAdd(&g_done, 1u);
        s_islast = (prev == NB - 1) ? 1 : 0;
    }
    __syncthreads();

    // --- last block performs the final deterministic reduction ---
    if (s_islast) {
        float4 a = __ldcg(&g_part[tid]);
        float4 b = __ldcg(&g_part[tid + NT]);
        s_rf[tid] = make_float4(a.x + b.x, a.y + b.y, a.z + b.z, 0.0f);
        __syncthreads();
        #pragma unroll
        for (int s = NT / 2; s > 0; s >>= 1) {
            if (tid < s) {
                float4 x0 = s_rf[tid];
                float4 x1 = s_rf[tid + s];
                s_rf[tid] = make_float4(x0.x + x1.x, x0.y + x1.y, x0.z + x1.z, 0.0f);
            }
            __syncthreads();
        }
        if (tid == 0) {
            float4 rres = s_rf[0];
            float count = rres.y;
            float loss1 = (count > 0.0f) ? (rres.x / fmaxf(count, 1.0f)) : 0.0f;
            float loss2 = LAM * rres.z / (float)(NN * BIT);
            out[0] = loss1 + loss2;
            g_done = 0;   // reset for next graph replay (safe: we are last)
        }
    }
}

// ---------------------------------------------------------------------------
extern "C" void kernel_launch(void* const* d_in, const int* in_sizes, int n_in,
                              void* d_out, int out_size) {
    const float* u;
    const float* y;
    if (in_sizes[0] == NN * BIT) {
        u = (const float*)d_in[0];
        y = (const float*)d_in[1];
    } else {
        u = (const float*)d_in[1];
        y = (const float*)d_in[0];
    }
    float* out = (float*)d_out;

    fused_kernel<<<NB, NT>>>(u, y, out);
}

// round 14
// speedup vs baseline: 1.1555x; 1.0022x over previous
#include <cuda_runtime.h>
#include <math.h>

#define NN    512
#define BIT   64
#define NCLS  100
#define ALPHA 5.0f
#define LAM   1.0f
#define RPB   2                 // anchor rows per block
#define NB    (NN / RPB)        // 256 blocks
#define NT    512               // threads per block (16 warps)

// Scratch (allocation-free: __device__ globals)
__device__ float4 g_part[NB];    // {bsum, bcnt, bl2, 0} per block
__device__ unsigned int g_done = 0;

// ---------------------------------------------------------------------------
// Single fused kernel: 256 blocks x 512 threads (same 4096-warp pool as R13
// but HALF the u LDG traffic). Two anchor rows per block; each thread owns
// exactly one n-column. 2-level shuffle dot + deferred quarter reduction.
// ---------------------------------------------------------------------------
__global__ void __launch_bounds__(NT) fused_kernel(const float* __restrict__ u,
                                                   const float* __restrict__ y,
                                                   float* __restrict__ out) {
    __shared__ float4 s_ur[RPB][BIT / 4];          // anchor rows of u     (512 B)
    __shared__ float4 s_pp[RPB][NN];               // quarter partials     (16 KB)
    __shared__ float  s_ip[RPB][NN];               // ip rows              (4 KB)
    __shared__ int    s_lbl[RPB];
    __shared__ unsigned s_gmask[RPB][16];          // pos bitmask words
    __shared__ short  s_poslist[RPB][NN];          // positive indices     (2 KB)
    __shared__ float  s_part[RPB][16];             // per-warp pair partials
    __shared__ float  s_s2[4];                     // loss2 partials
    __shared__ int    s_islast;
    __shared__ float4 s_rf[NB];                    // final reduce scratch (4 KB)

    const int tid  = threadIdx.x;
    const int bid  = blockIdx.x;
    const int r0   = bid * RPB;
    const int lane = tid & 31;
    const int wrp  = tid >> 5;                     // 0..15

    // --- phase 0: anchor rows of u into smem + label recovery (one-hot) ---
    if (tid < RPB * (BIT / 4)) {                   // 32 float4 loads
        int i = tid >> 4;
        int k = tid & 15;
        s_ur[i][k] = ((const float4*)(u + (size_t)(r0 + i) * BIT))[k];
    }
    if (tid < RPB * NCLS) {                        // 200 <= 512, one writer/row
        int i = tid / NCLS;
        int c = tid % NCLS;
        if (y[(size_t)(r0 + i) * NCLS + c] > 0.5f) s_lbl[i] = c;
    }
    __syncthreads();                               // barrier 1

    const int lbl0 = s_lbl[0];
    const int lbl1 = s_lbl[1];

    // --- scattered isneg gathers issued EARLY; hide under the dot loop ---
    const float yv0 = __ldg(y + (size_t)tid * NCLS + lbl0);   // row0, j = tid
    const float yv1 = __ldg(y + (size_t)tid * NCLS + lbl1);   // row1, j = tid

    // --- coalesced dot phase: 32 rows / iter, 2 anchors, 2-level shuffle ---
    {
        const float4 av0 = s_ur[0][tid & 15];
        const float4 av1 = s_ur[1][tid & 15];
        const int row_in_iter = tid >> 4;          // 0..31
        const int q = (lane >> 2) & 3;             // quarter within row
        const bool writer = ((lane & 3) == 0);
        #pragma unroll 8
        for (int it = 0; it < NN / 32; ++it) {     // 16 iterations
            float4 b = ((const float4*)u)[it * (32 * BIT / 4) + tid];
            float p0 = av0.x * b.x + av0.y * b.y + av0.z * b.z + av0.w * b.w;
            float p1 = av1.x * b.x + av1.y * b.y + av1.z * b.z + av1.w * b.w;
            p0 += __shfl_xor_sync(0xffffffffu, p0, 1);
            p0 += __shfl_xor_sync(0xffffffffu, p0, 2);
            p1 += __shfl_xor_sync(0xffffffffu, p1, 1);
            p1 += __shfl_xor_sync(0xffffffffu, p1, 2);
            if (writer) {
                int row = it * 32 + row_in_iter;
                ((float*)&s_pp[0][row])[q] = p0;
                ((float*)&s_pp[1][row])[q] = p1;
            }
        }
    }

    // --- isneg in registers (one-hot: exact 0/1); ballots from registers ---
    const bool n0 = (yv0 == 0.0f);                 // true = negative pair
    const bool n1 = (yv1 == 0.0f);
    {
        unsigned m;
        m = __ballot_sync(0xffffffffu, !n0);       // positives, j = wrp*32+lane
        if (lane == 0) s_gmask[0][wrp] = m;
        m = __ballot_sync(0xffffffffu, !n1);
        if (lane == 0) s_gmask[1][wrp] = m;
    }

    // --- loss2 partial: this block's RPB*BIT = 128 u values (smem copy) ---
    if (tid < RPB * BIT) {
        float v  = ((const float*)s_ur)[tid];
        float sg = (v > 0.0f) ? 1.0f : ((v < 0.0f) ? -1.0f : 0.0f);
        float d  = v - sg;
        float s2 = d * d;
        #pragma unroll
        for (int o = 16; o > 0; o >>= 1) s2 += __shfl_xor_sync(0xffffffffu, s2, o);
        if (lane == 0) s_s2[wrp] = s2;
    }
    __syncthreads();                               // barrier 2

    // --- deferred row reduction: own-column ip values straight to registers ---
    float4 qa = s_pp[0][tid];
    float4 qb = s_pp[1][tid];
    const float ip0 = (qa.x + qa.y) + (qa.z + qa.w);
    const float ip1 = (qb.x + qb.y) + (qb.z + qb.w);
    s_ip[0][tid] = ip0;
    s_ip[1][tid] = ip1;

    // --- fully parallel rank-based compaction (both rows) ---
    int npos0 = 0, npos1 = 0;
    {
        int rank0 = 0, rank1 = 0;
        #pragma unroll
        for (int c = 0; c < 16; ++c) {
            int p0 = __popc(s_gmask[0][c]);
            int p1 = __popc(s_gmask[1][c]);
            if (c < wrp) { rank0 += p0; rank1 += p1; }
            npos0 += p0;
            npos1 += p1;
        }
        unsigned lanebits = (lane == 0) ? 0u : ((1u << lane) - 1u);
        rank0 += __popc(s_gmask[0][wrp] & lanebits);
        rank1 += __popc(s_gmask[1][wrp] & lanebits);
        if (!n0) s_poslist[0][rank0] = (short)tid;
        if (!n1) s_poslist[1][rank1] = (short)tid;
    }
    __syncthreads();                               // barrier 3

    // --- inverted pair loops: thread owns n = tid for both rows ---
    {
        float acc0 = 0.0f;
        for (int k = 0; k < npos0; ++k) {
            float ipp = s_ip[0][s_poslist[0][k]] - ALPHA;   // broadcast LDS
            if (n0) {
                float t = ipp - ip0;
                t = fminf(fmaxf(t, -100.0f), 50.0f);
                acc0 += __logf(1.0f + __expf(-fabsf(t))) + fmaxf(-t, 0.0f);
            }
        }
        #pragma unroll
        for (int o = 16; o > 0; o >>= 1) acc0 += __shfl_xor_sync(0xffffffffu, acc0, o);
        if (lane == 0) s_part[0][wrp] = acc0;

        float acc1 = 0.0f;
        for (int k = 0; k < npos1; ++k) {
            float ipp = s_ip[1][s_poslist[1][k]] - ALPHA;
            if (n1) {
                float t = ipp - ip1;
                t = fminf(fmaxf(t, -100.0f), 50.0f);
                acc1 += __logf(1.0f + __expf(-fabsf(t))) + fmaxf(-t, 0.0f);
            }
        }
        #pragma unroll
        for (int o = 16; o > 0; o >>= 1) acc1 += __shfl_xor_sync(0xffffffffu, acc1, o);
        if (lane == 0) s_part[1][wrp] = acc1;
    }
    __syncthreads();                               // barrier 4

    // --- block epilogue: 2 row losses + loss2 partial, publish ---
    if (tid == 0) {
        float bsum = 0.0f, bcnt = 0.0f;
        const int nposv[RPB] = {npos0, npos1};
        #pragma unroll
        for (int g = 0; g < RPB; ++g) {
            int   np = nposv[g];
            int   nn = NN - np;
            float rs = 0.0f;
            #pragma unroll
            for (int w2 = 0; w2 < 16; ++w2) rs += s_part[g][w2];
            float rl = rs / fmaxf((float)(np * nn), 1.0f);
            if (np > 0 && nn > 0) { bsum += rl; bcnt += 1.0f; }
        }
        float bl2 = s_s2[0] + s_s2[1] + s_s2[2] + s_s2[3];

        g_part[bid] = make_float4(bsum, bcnt, bl2, 0.0f);
        __threadfence();
        unsigned prev = atomicAdd(&g_done, 1u);
        s_islast = (prev == NB - 1) ? 1 : 0;
    }
    __syncthreads();

    // --- last block performs the final deterministic reduction ---
    if (s_islast) {
        if (tid < NB) s_rf[tid] = __ldcg(&g_part[tid]);
        __syncthreads();
        #pragma unroll
        for (int s = NB / 2; s > 0; s >>= 1) {
            if (tid < s) {
                float4 x0 = s_rf[tid];
                float4 x1 = s_rf[tid + s];
                s_rf[tid] = make_float4(x0.x + x1.x, x0.y + x1.y, x0.z + x1.z, 0.0f);
            }
            __syncthreads();
        }
        if (tid == 0) {
            float4 rres = s_rf[0];
            float count = rres.y;
            float loss1 = (count > 0.0f) ? (rres.x / fmaxf(count, 1.0f)) : 0.0f;
            float loss2 = LAM * rres.z / (float)(NN * BIT);
            out[0] = loss1 + loss2;
            g_done = 0;   // reset for next graph replay (safe: we are last)
        }
    }
}

// ---------------------------------------------------------------------------
extern "C" void kernel_launch(void* const* d_in, const int* in_sizes, int n_in,
                              void* d_out, int out_size) {
    const float* u;
    const float* y;
    if (in_sizes[0] == NN * BIT) {
        u = (const float*)d_in[0];
        y = (const float*)d_in[1];
    } else {
        u = (const float*)d_in[1];
        y = (const float*)d_in[0];
    }
    float* out = (float*)d_out;

    fused_kernel<<<NB, NT>>>(u, y, out);
}